// round 6
// baseline (speedup 1.0000x reference)
#include <cuda_runtime.h>

#define B_    4
#define C_    128
#define W_    128
#define H_    128
#define DWIN  21
#define PADN  10
#define KC    2                    // channels per staged chunk
#define NWARP 7
#define THREADS (NWARP * 32)
#define JBLK   128                 // full row per block
#define SHIFT  12                  // staged window starts at col -12 (16B aligned)
#define ROWLEN 152                 // cols -12..139 -> 38 float4 groups
#define NG1    (ROWLEN / 4)        // 38
#define NCHUNK (C_ / KC)           // 64

__global__ __launch_bounds__(THREADS, 2)
void corr_kernel(const float* __restrict__ x1,
                 const float* __restrict__ x2,
                 float* __restrict__ out)
{
    __shared__ __align__(16) float s_x1[NWARP][KC][ROWLEN]; // 7*2*152*4 = 8512 B
    __shared__ __align__(16) float s_x2[KC][JBLK];          // 2*128*4   = 1024 B

    const int dig = blockIdx.x;        // 0..2
    const int i   = blockIdx.y;        // 0..127
    const int b   = blockIdx.z;        // 0..3
    const int di0 = dig * NWARP;

    const int tid  = threadIdx.x;
    const int warp = tid >> 5;         // di = di0 + warp
    const int lane = tid & 31;         // j = 4*lane .. 4*lane+3

    const int row   = i + di0 + warp - PADN;
    const bool rowok = (row >= 0) && (row < W_);

    const float* x1b = x1 + (size_t)b * C_ * W_ * H_;
    const float* x2b = x2 + (size_t)b * C_ * W_ * H_ + (size_t)i * H_;

    // x1 staging: lane owns float4 groups {lane, lane+32} of each channel row
    const int colA  = 4 * lane - SHIFT;            // group lane
    const int colB  = colA + 128;                  // group lane+32 (only lanes<6)
    const bool aok  = rowok && (colA >= 0) && (colA < H_);
    const bool bok  = rowok && (lane < NG1 - 32) && (colB >= 0) && (colB < H_);
    const float* rowsrc = x1b + (size_t)row * H_;
    // x2 staging: threads 0..63 own one float4 group (c = tid>>5, g = tid&31)
    const bool g2ok = (tid < KC * 32);
    const int  x2c  = tid >> 5;
    const int  x2g  = tid & 31;
    const float* g2src = x2b + (size_t)x2c * (W_ * H_) + 4 * x2g;

    float acc[DWIN][4];
#pragma unroll
    for (int dj = 0; dj < DWIN; dj++) {
        acc[dj][0] = 0.f; acc[dj][1] = 0.f; acc[dj][2] = 0.f; acc[dj][3] = 0.f;
    }

    float4 rA[KC], rB[KC], r2;
    const float4 z4 = make_float4(0.f, 0.f, 0.f, 0.f);

    // ---- prologue: load chunk 0 ----
#pragma unroll
    for (int c = 0; c < KC; c++) {
        rA[c] = aok ? *(const float4*)(rowsrc + (size_t)c * (W_ * H_) + colA) : z4;
        rB[c] = bok ? *(const float4*)(rowsrc + (size_t)c * (W_ * H_) + colB) : z4;
    }
    r2 = g2ok ? *(const float4*)g2src : z4;

    for (int k = 0; k < NCHUNK; k++) {
        __syncthreads();   // compute on previous chunk finished

        // ---- store staged registers (chunk k) into smem ----
#pragma unroll
        for (int c = 0; c < KC; c++) {
            *(float4*)(&s_x1[warp][c][4 * lane]) = rA[c];
            if (lane < NG1 - 32)
                *(float4*)(&s_x1[warp][c][4 * lane + 128]) = rB[c];
        }
        if (g2ok)
            *(float4*)(&s_x2[x2c][4 * x2g]) = r2;
        __syncthreads();

        // ---- prefetch chunk k+1 into registers ----
        if (k + 1 < NCHUNK) {
            const size_t coff = (size_t)(k + 1) * KC * (W_ * H_);
#pragma unroll
            for (int c = 0; c < KC; c++) {
                const float* s = rowsrc + coff + (size_t)c * (W_ * H_);
                rA[c] = aok ? *(const float4*)(s + colA) : z4;
                rB[c] = bok ? *(const float4*)(s + colB) : z4;
            }
            r2 = g2ok ? *(const float4*)(g2src + coff) : z4;
        }

        // ---- compute chunk k: 84 FMAs per channel per thread ----
#pragma unroll
        for (int c = 0; c < KC; c++) {
            // staged col p <-> global col p-12; need j+dj-10 (j=4*lane) -> p = 4*lane+dj+2
            const float* xr = &s_x1[warp][c][4 * lane + 2];
            float w[24];
#pragma unroll
            for (int t = 0; t < 12; t++) {
                const float2 v = *(const float2*)(xr + 2 * t);   // 8B-aligned
                w[2*t]   = v.x;
                w[2*t+1] = v.y;
            }
            const float4 bv = *(const float4*)(&s_x2[c][4 * lane]);
#pragma unroll
            for (int dj = 0; dj < DWIN; dj++) {
                acc[dj][0] += w[dj]     * bv.x;
                acc[dj][1] += w[dj + 1] * bv.y;
                acc[dj][2] += w[dj + 2] * bv.z;
                acc[dj][3] += w[dj + 3] * bv.w;
            }
        }
    }

    // ---- write out[b, (di0+warp)*21+dj, i, 4*lane .. +3] ----
    const int di = di0 + warp;
    float* ob = out + (((size_t)b * (DWIN * DWIN) + (size_t)di * DWIN) * W_ + i) * H_
                    + 4 * lane;
#pragma unroll
    for (int dj = 0; dj < DWIN; dj++) {
        *(float4*)(ob + (size_t)dj * (W_ * H_)) =
            make_float4(acc[dj][0], acc[dj][1], acc[dj][2], acc[dj][3]);
    }
}

extern "C" void kernel_launch(void* const* d_in, const int* in_sizes, int n_in,
                              void* d_out, int out_size)
{
    const float* x1 = (const float*)d_in[0];
    const float* x2 = (const float*)d_in[1];
    float* out = (float*)d_out;

    dim3 grid(3, W_, B_);   // (dig, i, b)
    corr_kernel<<<grid, THREADS>>>(x1, x2, out);
}